// round 5
// baseline (speedup 1.0000x reference)
#include <cuda_runtime.h>
#include <cfloat>

// Reverse cummax along axis 1 of [B=16, H=128, W=128, C=256] fp32.
// One thread per (b, w, c4) float4-column; walk h backward with running max.
// R4: 64-thread CTAs (2048 blocks) for finer tail granularity under the
// per-SM completion-spread floor; load-batch/store-batch separated in an
// unroll-4 window to reduce per-warp read<->write turnaround.

static constexpr int B = 16;
static constexpr int H = 128;
static constexpr int W = 128;
static constexpr int C = 256;
static constexpr int C4 = C / 4;            // 64 float4 per row
static constexpr int STRIDE_H = W * C4;     // 8192 float4 between h slices
static constexpr int COLS = B * W * C4;     // 131072 columns
static constexpr int PER_B = W * C4;        // 8192 columns per batch
static constexpr long PER_B_ELEMS = (long)H * W * C4;
static constexpr int UN = 4;

__global__ void __launch_bounds__(64) rev_cummax_kernel(
    const float4* __restrict__ in, float4* __restrict__ out)
{
    int col = blockIdx.x * blockDim.x + threadIdx.x;

    int b   = col >> 13;            // col / 8192
    int rem = col & (PER_B - 1);
    long top = (long)b * PER_B_ELEMS + rem + (long)(H - 1) * STRIDE_H;

    const float4* p = in  + top;
    float4*       q = out + top;

    float4 m = make_float4(-FLT_MAX, -FLT_MAX, -FLT_MAX, -FLT_MAX);

    #pragma unroll 1
    for (int it = 0; it < H / UN; ++it) {
        float4 v[UN];
        #pragma unroll
        for (int j = 0; j < UN; ++j)
            v[j] = p[-(long)j * STRIDE_H];

        float4 r[UN];
        #pragma unroll
        for (int j = 0; j < UN; ++j) {
            m.x = fmaxf(m.x, v[j].x);
            m.y = fmaxf(m.y, v[j].y);
            m.z = fmaxf(m.z, v[j].z);
            m.w = fmaxf(m.w, v[j].w);
            r[j] = m;
        }

        #pragma unroll
        for (int j = 0; j < UN; ++j)
            q[-(long)j * STRIDE_H] = r[j];

        p -= (long)UN * STRIDE_H;
        q -= (long)UN * STRIDE_H;
    }
}

extern "C" void kernel_launch(void* const* d_in, const int* in_sizes, int n_in,
                              void* d_out, int out_size)
{
    (void)in_sizes; (void)n_in; (void)out_size;
    const float4* in  = (const float4*)d_in[0];
    float4*       out = (float4*)d_out;

    const int threads = 64;
    const int blocks  = COLS / threads;  // 2048, exact
    rev_cummax_kernel<<<blocks, threads>>>(in, out);
}